// round 14
// baseline (speedup 1.0000x reference)
#include <cuda_runtime.h>
#include <cuda_fp16.h>
#include <math_constants.h>

#define N_NODES 100000
#define N_EDGES 200000
#define NG      2000
#define H       32

typedef unsigned long long ull;

// ---------------- device scratch (alloc-free) ----------------
__device__ float  g_h[N_NODES * H];                 // node hidden fp32  12.8 MB
__device__ __half g_hh[N_NODES * H];                // node hidden fp16   6.4 MB
__device__ float  g_m[N_NODES * H];                 // aggregated msgs   12.8 MB
__device__ __half g_rh[(size_t)N_EDGES * 64];       // edge hidden fp16  25.6 MB
__device__ __half g_W2h[1024 * 64];                 // W2 fp16 transposed [n][k], 128 KB
__device__ __half g_GWh[192 * 64];                  // GRU weights fp16 block-diag
__device__ uint4  g_A4[(size_t)N_EDGES * 128];      // edge matrices fp16, 409.6 MB
__device__ int    g_offs[NG + 1];                   // graph segment offsets

// ---------------- helpers ----------------
__device__ __forceinline__ float warpMax(float v) {
    #pragma unroll
    for (int o = 16; o > 0; o >>= 1) v = fmaxf(v, __shfl_xor_sync(0xffffffffu, v, o));
    return v;
}
__device__ __forceinline__ float warpSum(float v) {
    #pragma unroll
    for (int o = 16; o > 0; o >>= 1) v += __shfl_xor_sync(0xffffffffu, v, o);
    return v;
}
__device__ __forceinline__ float sigm(float x) { return 1.0f / (1.0f + expf(-x)); }

// ---------------- W2 pack: g_W2h[n][k] = fp16(W2[k][n]) ----------------
__global__ void k_packW2(const float* __restrict__ W2) {
    int i = blockIdx.x * blockDim.x + threadIdx.x;
    if (i >= 64 * 1024) return;
    int k = i >> 10, n = i & 1023;
    g_W2h[n * 64 + k] = __float2half_rn(W2[i]);
}

// ---------------- GRU weight pack: block-diagonal [192][64] fp16 --------------
__global__ void k_packGW(const float* __restrict__ Wih, const float* __restrict__ Whh) {
    int i = blockIdx.x * blockDim.x + threadIdx.x;
    if (i >= 192 * 64) return;
    int n = i >> 6, k = i & 63;
    float v = 0.0f;
    if (n < 96 && k < 32) v = Wih[n * 32 + k];
    else if (n >= 96 && k >= 32) v = Whh[(n - 96) * 32 + (k - 32)];
    g_GWh[n * 64 + k] = __float2half_rn(v);
}

// ---------------- encoder: h = nf @ enc_W + enc_b; writes fp16 mirror; zeros m
__global__ void k_encode(const float* __restrict__ nf, const float* __restrict__ W,
                         const float* __restrict__ b) {
    __shared__ float sW[16 * 32];
    __shared__ float sb[32];
    int t = threadIdx.x;
    for (int i = t; i < 512; i += 256) sW[i] = W[i];
    if (t < 32) sb[t] = b[t];
    __syncthreads();
    int n = blockIdx.x * blockDim.x + t;
    if (n >= N_NODES) return;
    float x[16];
    const float4* p = (const float4*)(nf + (long long)n * 16);
    #pragma unroll
    for (int q = 0; q < 4; q++) {
        float4 v = p[q];
        x[q*4+0] = v.x; x[q*4+1] = v.y; x[q*4+2] = v.z; x[q*4+3] = v.w;
    }
    float hv[32];
    #pragma unroll
    for (int c = 0; c < 32; c++) {
        float acc = sb[c];
        #pragma unroll
        for (int d = 0; d < 16; d++) acc += x[d] * sW[d * 32 + c];
        hv[c] = acc;
    }
    float4* hp = (float4*)&g_h[n * 32];
    float4* mz = (float4*)&g_m[n * 32];
    __half2* hh = (__half2*)&g_hh[n * 32];
    #pragma unroll
    for (int q = 0; q < 8; q++) {
        hp[q] = make_float4(hv[q*4], hv[q*4+1], hv[q*4+2], hv[q*4+3]);
        mz[q] = make_float4(0.f, 0.f, 0.f, 0.f);
    }
    #pragma unroll
    for (int c2 = 0; c2 < 16; c2++)
        hh[c2] = __floats2half2_rn(hv[2*c2], hv[2*c2+1]);
}

// ---------------- edge hidden: rh = fp16(relu(ef @ e_W1 + e_b1)) ----------------
__global__ void k_edgehid(const float* __restrict__ ef, const float* __restrict__ W,
                          const float* __restrict__ b) {
    __shared__ float sW[8 * 64];
    __shared__ float sb[64];
    int t = threadIdx.x;
    for (int i = t; i < 512; i += 256) sW[i] = W[i];
    if (t < 64) sb[t] = b[t];
    __syncthreads();
    int e = blockIdx.x * blockDim.x + t;
    if (e >= N_EDGES) return;
    float x[8];
    const float4* p = (const float4*)(ef + (long long)e * 8);
    float4 v0 = p[0], v1 = p[1];
    x[0]=v0.x; x[1]=v0.y; x[2]=v0.z; x[3]=v0.w;
    x[4]=v1.x; x[5]=v1.y; x[6]=v1.z; x[7]=v1.w;
    float o[64];
    #pragma unroll
    for (int c = 0; c < 64; c++) {
        float acc = sb[c];
        #pragma unroll
        for (int d = 0; d < 8; d++) acc += x[d] * sW[d * 64 + c];
        o[c] = fmaxf(acc, 0.0f);
    }
    __half2* dst = (__half2*)&g_rh[(size_t)e * 64];
    #pragma unroll
    for (int c2 = 0; c2 < 32; c2++)
        dst[c2] = __floats2half2_rn(o[2 * c2], o[2 * c2 + 1]);
}

// ---------------- A GEMM (once): A[E,1024] = rh[E,64] @ W2 + b2, fp16 out ------
// BM=128, BN=128, K=64 one-shot. 8 warps (2Mx4N), warp tile 64x32.
// Validated fragment/epilogue layout (R5); Wt loaded coalesced from g_W2h.
#define ROWP 72
__global__ void __launch_bounds__(256) k_gemmA(const float* __restrict__ b2) {
    __shared__ __half Rs[128 * ROWP];   // rh tile [m][k] 18 KB
    __shared__ __half Wt[128 * ROWP];   // W2 tile [n][k] 18 KB
    int t    = threadIdx.x;
    int lane = t & 31;
    int wid  = t >> 5;
    int e0   = blockIdx.y * 128;
    int n0   = blockIdx.x * 128;
    int warpM = (wid & 1) * 64;
    int warpN = (wid >> 1) * 32;

    // load rh tile [128 x 64] fp16
    #pragma unroll
    for (int i = 0; i < 4; i++) {
        int g   = t + 256 * i;
        int row = g >> 3;
        int kg  = g & 7;
        uint4 v = make_uint4(0u, 0u, 0u, 0u);
        int e = e0 + row;
        if (e < N_EDGES) v = *(const uint4*)&g_rh[(size_t)e * 64 + kg * 8];
        *(uint4*)&Rs[row * ROWP + kg * 8] = v;
    }
    // load W2 tile [128 n x 64 k] fp16 (prepacked transposed)
    #pragma unroll
    for (int i = 0; i < 4; i++) {
        int g   = t + 256 * i;
        int row = g >> 3;
        int kg  = g & 7;
        *(uint4*)&Wt[row * ROWP + kg * 8] =
            *(const uint4*)&g_W2h[(size_t)(n0 + row) * 64 + kg * 8];
    }
    __syncthreads();

    int aRow  = warpM + (lane & 15);
    int aColB = (lane >> 4) << 3;
    int bRow  = warpN + (lane & 7) + ((lane >> 4) << 3);
    int bColB = ((lane >> 3) & 1) << 3;

    float acc[4][4][4];
    #pragma unroll
    for (int mt = 0; mt < 4; mt++)
        #pragma unroll
        for (int nt = 0; nt < 4; nt++)
            #pragma unroll
            for (int q = 0; q < 4; q++) acc[mt][nt][q] = 0.0f;

    #pragma unroll
    for (int ks = 0; ks < 4; ks++) {
        int k0 = ks * 16;
        unsigned a[4][4];
        #pragma unroll
        for (int mt = 0; mt < 4; mt++) {
            unsigned addr = (unsigned)__cvta_generic_to_shared(
                &Rs[(aRow + mt * 16) * ROWP + k0 + aColB]);
            asm volatile("ldmatrix.sync.aligned.m8n8.x4.shared.b16 {%0,%1,%2,%3}, [%4];"
                         : "=r"(a[mt][0]), "=r"(a[mt][1]), "=r"(a[mt][2]), "=r"(a[mt][3])
                         : "r"(addr));
        }
        unsigned bf[4][2];
        #pragma unroll
        for (int p = 0; p < 2; p++) {
            unsigned addr = (unsigned)__cvta_generic_to_shared(
                &Wt[(bRow + p * 16) * ROWP + k0 + bColB]);
            asm volatile("ldmatrix.sync.aligned.m8n8.x4.shared.b16 {%0,%1,%2,%3}, [%4];"
                         : "=r"(bf[2*p][0]), "=r"(bf[2*p][1]),
                           "=r"(bf[2*p+1][0]), "=r"(bf[2*p+1][1])
                         : "r"(addr));
        }
        #pragma unroll
        for (int mt = 0; mt < 4; mt++)
            #pragma unroll
            for (int nt = 0; nt < 4; nt++) {
                asm volatile(
                    "mma.sync.aligned.m16n8k16.row.col.f32.f16.f16.f32 "
                    "{%0,%1,%2,%3}, {%4,%5,%6,%7}, {%8,%9}, {%0,%1,%2,%3};"
                    : "+f"(acc[mt][nt][0]), "+f"(acc[mt][nt][1]),
                      "+f"(acc[mt][nt][2]), "+f"(acc[mt][nt][3])
                    : "r"(a[mt][0]), "r"(a[mt][1]), "r"(a[mt][2]), "r"(a[mt][3]),
                      "r"(bf[nt][0]), "r"(bf[nt][1]));
            }
    }

    // epilogue: +bias, fp16 store
    __half* gA = (__half*)g_A4;
    int r0base = e0 + warpM + (lane >> 2);
    #pragma unroll
    for (int nt = 0; nt < 4; nt++) {
        int col = n0 + warpN + nt * 8 + (lane & 3) * 2;
        float2 bb = *(const float2*)&b2[col];
        #pragma unroll
        for (int mt = 0; mt < 4; mt++) {
            int r0 = r0base + mt * 16;
            if (r0 < N_EDGES)
                *(__half2*)&gA[(size_t)r0 * 1024 + col] =
                    __floats2half2_rn(acc[mt][nt][0] + bb.x, acc[mt][nt][1] + bb.y);
            int r1 = r0 + 8;
            if (r1 < N_EDGES)
                *(__half2*)&gA[(size_t)r1 * 1024 + col] =
                    __floats2half2_rn(acc[mt][nt][2] + bb.x, acc[mt][nt][3] + bb.y);
        }
    }
}

// ---------------- message pass: m[tgt] += A[e] @ h[src] (fp16 A, streamed) -----
// one warp per edge; lane i computes msg[i] = sum_j A[e, i*32+j] * h[src, j].
// A row read is 2KB contiguous per warp; atomics land on one 128B line per warp.
__global__ void __launch_bounds__(256) k_message(const int* __restrict__ ei) {
    int lane = threadIdx.x & 31;
    int e = (blockIdx.x * blockDim.x + threadIdx.x) >> 5;
    if (e >= N_EDGES) return;
    int src = ei[e];
    int tgt = ei[N_EDGES + e];
    float hv = __half2float(g_hh[src * 32 + lane]);
    const uint4* Ar = g_A4 + (size_t)e * 128 + lane * 4;
    float acc = 0.0f;
    #pragma unroll
    for (int u = 0; u < 4; u++) {
        uint4 a = Ar[u];
        float2 f0 = __half22float2(*(__half2*)&a.x);
        float2 f1 = __half22float2(*(__half2*)&a.y);
        float2 f2 = __half22float2(*(__half2*)&a.z);
        float2 f3 = __half22float2(*(__half2*)&a.w);
        acc += f0.x * __shfl_sync(0xffffffffu, hv, 8*u+0);
        acc += f0.y * __shfl_sync(0xffffffffu, hv, 8*u+1);
        acc += f1.x * __shfl_sync(0xffffffffu, hv, 8*u+2);
        acc += f1.y * __shfl_sync(0xffffffffu, hv, 8*u+3);
        acc += f2.x * __shfl_sync(0xffffffffu, hv, 8*u+4);
        acc += f2.y * __shfl_sync(0xffffffffu, hv, 8*u+5);
        acc += f3.x * __shfl_sync(0xffffffffu, hv, 8*u+6);
        acc += f3.y * __shfl_sync(0xffffffffu, hv, 8*u+7);
    }
    atomicAdd(&g_m[tgt * 32 + lane], acc);
}

// ---------------- GRU via tensor cores (validated R13) ----------------
#define GRU_SMEM 87808
__global__ void __launch_bounds__(256, 2) k_gru_mma(const float* __restrict__ bih,
                                                    const float* __restrict__ bhh) {
    extern __shared__ unsigned char dsm[];
    __half* Xs    = (__half*)dsm;                      // [64][72]
    __half* Ws    = (__half*)(dsm + 9216);             // [192][72]
    float*  sGate = (float*)(dsm + 36864);             // [64][196]
    float*  sbi   = (float*)(dsm + 87040);             // [96]
    float*  sbh   = (float*)(dsm + 87424);             // [96]

    int t = threadIdx.x, lane = t & 31, wid = t >> 5;
    int n0 = blockIdx.x * 64;

    {
        int row = t >> 2, quad = t & 3;
        int node = n0 + row;
        bool ok = node < N_NODES;
        if (quad < 2) {
            const float4* mp = (const float4*)&g_m[node * 32 + quad * 16];
            #pragma unroll
            for (int q = 0; q < 2; q++) {
                float4 v0 = ok ? mp[2*q]   : make_float4(0.f,0.f,0.f,0.f);
                float4 v1 = ok ? mp[2*q+1] : make_float4(0.f,0.f,0.f,0.f);
                uint4 u;
                __half2 h0 = __floats2half2_rn(v0.x, v0.y); u.x = *(unsigned*)&h0;
                __half2 h1 = __floats2half2_rn(v0.z, v0.w); u.y = *(unsigned*)&h1;
                __half2 h2 = __floats2half2_rn(v1.x, v1.y); u.z = *(unsigned*)&h2;
                __half2 h3 = __floats2half2_rn(v1.z, v1.w); u.w = *(unsigned*)&h3;
                *(uint4*)&Xs[row * 72 + quad * 16 + q * 8] = u;
            }
        } else {
            const uint4* hp = (const uint4*)&g_hh[node * 32 + (quad - 2) * 16];
            #pragma unroll
            for (int q = 0; q < 2; q++) {
                uint4 v = ok ? hp[q] : make_uint4(0u,0u,0u,0u);
                *(uint4*)&Xs[row * 72 + 32 + (quad - 2) * 16 + q * 8] = v;
            }
        }
    }
    #pragma unroll
    for (int j = 0; j < 6; j++) {
        int i = t + 256 * j;
        int rowW = i >> 3, kg = i & 7;
        *(uint4*)&Ws[rowW * 72 + kg * 8] = *(const uint4*)&g_GWh[rowW * 64 + kg * 8];
    }
    if (t < 96) sbi[t] = bih[t];
    else if (t < 192) sbh[t - 96] = bhh[t - 96];
    __syncthreads();

    int warpM = (wid & 1) * 32;
    int warpN = (wid >> 1) * 48;
    int aRow  = warpM + (lane & 15);
    int aColB = (lane >> 4) << 3;
    int bRow  = warpN + (lane & 7) + ((lane >> 4) << 3);
    int bColB = ((lane >> 3) & 1) << 3;

    float acc[2][6][4];
    #pragma unroll
    for (int mt = 0; mt < 2; mt++)
        #pragma unroll
        for (int nt = 0; nt < 6; nt++)
            #pragma unroll
            for (int q = 0; q < 4; q++) acc[mt][nt][q] = 0.0f;

    #pragma unroll
    for (int ks = 0; ks < 4; ks++) {
        int k0 = ks * 16;
        unsigned a[2][4];
        #pragma unroll
        for (int mt = 0; mt < 2; mt++) {
            unsigned addr = (unsigned)__cvta_generic_to_shared(
                &Xs[(aRow + mt * 16) * 72 + k0 + aColB]);
            asm volatile("ldmatrix.sync.aligned.m8n8.x4.shared.b16 {%0,%1,%2,%3}, [%4];"
                         : "=r"(a[mt][0]), "=r"(a[mt][1]), "=r"(a[mt][2]), "=r"(a[mt][3])
                         : "r"(addr));
        }
        unsigned bf[6][2];
        #pragma unroll
        for (int p = 0; p < 3; p++) {
            unsigned addr = (unsigned)__cvta_generic_to_shared(
                &Ws[(bRow + p * 16) * 72 + k0 + bColB]);
            asm volatile("ldmatrix.sync.aligned.m8n8.x4.shared.b16 {%0,%1,%2,%3}, [%4];"
                         : "=r"(bf[2*p][0]), "=r"(bf[2*p][1]),
                           "=r"(bf[2*p+1][0]), "=r"(bf[2*p+1][1])
                         : "r"(addr));
        }
        #pragma unroll
        for (int mt = 0; mt < 2; mt++)
            #pragma unroll
            for (int nt = 0; nt < 6; nt++) {
                asm volatile(
                    "mma.sync.aligned.m16n8k16.row.col.f32.f16.f16.f32 "
                    "{%0,%1,%2,%3}, {%4,%5,%6,%7}, {%8,%9}, {%0,%1,%2,%3};"
                    : "+f"(acc[mt][nt][0]), "+f"(acc[mt][nt][1]),
                      "+f"(acc[mt][nt][2]), "+f"(acc[mt][nt][3])
                    : "r"(a[mt][0]), "r"(a[mt][1]), "r"(a[mt][2]), "r"(a[mt][3]),
                      "r"(bf[nt][0]), "r"(bf[nt][1]));
            }
    }

    int r0base = warpM + (lane >> 2);
    #pragma unroll
    for (int nt = 0; nt < 6; nt++) {
        int col = warpN + nt * 8 + (lane & 3) * 2;
        #pragma unroll
        for (int mt = 0; mt < 2; mt++) {
            int r0 = r0base + mt * 16;
            *(float2*)&sGate[r0 * 196 + col] = make_float2(acc[mt][nt][0], acc[mt][nt][1]);
            *(float2*)&sGate[(r0 + 8) * 196 + col] = make_float2(acc[mt][nt][2], acc[mt][nt][3]);
        }
    }
    __syncthreads();

    #pragma unroll 1
    for (int idx = t; idx < 64 * 32; idx += 256) {
        int nd = idx >> 5, k = idx & 31;
        int node = n0 + nd;
        if (node >= N_NODES) continue;
        const float* gr = &sGate[nd * 196];
        float gir = gr[k]        + sbi[k];
        float giz = gr[32 + k]   + sbi[32 + k];
        float gin = gr[64 + k]   + sbi[64 + k];
        float ghr = gr[96 + k]   + sbh[k];
        float ghz = gr[128 + k]  + sbh[32 + k];
        float ghn = gr[160 + k]  + sbh[64 + k];
        float r = sigm(gir + ghr);
        float z = sigm(giz + ghz);
        float nn = tanhf(gin + r * ghn);
        float hold = g_h[node * 32 + k];
        float hnew = (1.0f - z) * nn + z * hold;
        g_h[node * 32 + k]  = hnew;
        g_hh[node * 32 + k] = __float2half_rn(hnew);
        g_m[node * 32 + k]  = 0.0f;
    }
}

// ---------------- graph segment offsets (batch_indices sorted) ----------------
__global__ void k_offs(const int* __restrict__ batch) {
    int n = blockIdx.x * blockDim.x + threadIdx.x;
    if (n >= N_NODES) return;
    int b = batch[n];
    int prev = (n == 0) ? -1 : batch[n - 1];
    for (int g = prev + 1; g <= b; g++) g_offs[g] = n;
    if (n == N_NODES - 1)
        for (int g = b + 1; g <= NG; g++) g_offs[g] = N_NODES;
}

// ---------------- FUSED Set2Set: 4x(attend+LSTM) + output head, 1 warp/graph --
__global__ void __launch_bounds__(256) k_s2s(const float* __restrict__ lWih,
                                             const float* __restrict__ lWhh,
                                             const float* __restrict__ lbih,
                                             const float* __restrict__ lbhh,
                                             const float* __restrict__ oW1,
                                             const float* __restrict__ ob1,
                                             const float* __restrict__ oW2,
                                             const float* __restrict__ ob2,
                                             float* __restrict__ out) {
    __shared__ float sWa[128 * 33];
    __shared__ float sWb[128 * 33];
    __shared__ float sbias[128];
    __shared__ float sW1[64 * 32];
    __shared__ float sW2[96];
    __shared__ float sb1o[32];
    __shared__ float sb2o[3];
    int t = threadIdx.x, lane = t & 31, wid = t >> 5;

    for (int i = t; i < 128 * 32; i += 256) {
        int k = i >> 5, c = i & 31;
        sWa[k * 33 + c] = lWih[k * 64 + c] + lWhh[k * 32 + c];
        sWb[k * 33 + c] = lWih[k * 64 + 32 + c];
    }
    if (t < 128) sbias[t] = lbih[t] + lbhh[t];
    for (int i = t; i < 2048; i += 256) sW1[i] = oW1[i];
    if (t < 96) sW2[t] = oW2[t];
    if (t < 32) sb1o[t] = ob1[t];
    if (t < 3)  sb2o[t] = ob2[t];
    __syncthreads();

    int g = blockIdx.x * 8 + wid;
    if (g >= NG) return;
    int s = g_offs[g], tEnd = g_offs[g + 1];

    float sh = 0.0f, cst = 0.0f, rr = 0.0f;

    #pragma unroll 1
    for (int step = 0; step < 4; step++) {
        float q = sh;
        float maxv = -CUDART_INF_F, denom = 0.0f, racc = 0.0f;
        for (int base = s; base < tEnd; base += 32) {
            int n = base + lane;
            bool act = n < tEnd;
            int nn = act ? n : s;
            float rv[32];
            const float4* hp4 = (const float4*)&g_h[nn * 32];
            #pragma unroll
            for (int q4 = 0; q4 < 8; q4++) {
                float4 v = hp4[q4];
                rv[q4*4] = v.x; rv[q4*4+1] = v.y; rv[q4*4+2] = v.z; rv[q4*4+3] = v.w;
            }
            float ev = 0.0f;
            #pragma unroll
            for (int j = 0; j < 32; j++)
                ev += rv[j] * __shfl_sync(0xffffffffu, q, j);
            float e_n = act ? ev : -CUDART_INF_F;
            float cm = warpMax(e_n);
            float nm = fmaxf(maxv, cm);
            float scale = (maxv == -CUDART_INF_F) ? 0.0f : expf(maxv - nm);
            float p = act ? expf(e_n - nm) : 0.0f;
            float ps = warpSum(p);
            denom = denom * scale + ps;
            racc *= scale;
            maxv = nm;
            int cnt = min(32, tEnd - base);
            for (int n2 = 0; n2 < cnt; n2++) {
                float pn = __shfl_sync(0xffffffffu, p, n2);
                racc += pn * g_h[(base + n2) * 32 + lane];
            }
        }
        rr = (denom > 0.0f) ? (racc / denom) : 0.0f;

        float ai = sbias[lane];
        float af = sbias[32 + lane];
        float ag = sbias[64 + lane];
        float ao = sbias[96 + lane];
        #pragma unroll 1
        for (int c = 0; c < 32; c++) {
            float shv = __shfl_sync(0xffffffffu, sh, c);
            float rvv = __shfl_sync(0xffffffffu, rr, c);
            ai += shv * sWa[lane * 33 + c]        + rvv * sWb[lane * 33 + c];
            af += shv * sWa[(32 + lane) * 33 + c] + rvv * sWb[(32 + lane) * 33 + c];
            ag += shv * sWa[(64 + lane) * 33 + c] + rvv * sWb[(64 + lane) * 33 + c];
            ao += shv * sWa[(96 + lane) * 33 + c] + rvv * sWb[(96 + lane) * 33 + c];
        }
        float i_ = sigm(ai), f_ = sigm(af), gv = tanhf(ag), o_ = sigm(ao);
        cst = f_ * cst + i_ * gv;
        sh = o_ * tanhf(cst);
    }

    float hid = sb1o[lane];
    #pragma unroll 1
    for (int d = 0; d < 32; d++) {
        float shv = __shfl_sync(0xffffffffu, sh, d);
        float rvv = __shfl_sync(0xffffffffu, rr, d);
        hid += shv * sW1[d * 32 + lane] + rvv * sW1[(32 + d) * 32 + lane];
    }
    hid = fmaxf(hid, 0.0f);
    float o0 = hid * sW2[lane * 3 + 0];
    float o1 = hid * sW2[lane * 3 + 1];
    float o2 = hid * sW2[lane * 3 + 2];
    o0 = warpSum(o0); o1 = warpSum(o1); o2 = warpSum(o2);
    if (lane == 0) {
        out[g * 3 + 0] = o0 + sb2o[0];
        out[g * 3 + 1] = o1 + sb2o[1];
        out[g * 3 + 2] = o2 + sb2o[2];
    }
}

// ---------------- launch ----------------
extern "C" void kernel_launch(void* const* d_in, const int* in_sizes, int n_in,
                              void* d_out, int out_size) {
    const float* nf     = (const float*)d_in[0];
    const float* ef     = (const float*)d_in[1];
    const float* enc_W  = (const float*)d_in[2];
    const float* enc_b  = (const float*)d_in[3];
    const float* e_W1   = (const float*)d_in[4];
    const float* e_b1   = (const float*)d_in[5];
    const float* e_W2   = (const float*)d_in[6];
    const float* e_b2   = (const float*)d_in[7];
    const float* gWih   = (const float*)d_in[8];
    const float* gWhh   = (const float*)d_in[9];
    const float* gbih   = (const float*)d_in[10];
    const float* gbhh   = (const float*)d_in[11];
    const float* lWih   = (const float*)d_in[12];
    const float* lWhh   = (const float*)d_in[13];
    const float* lbih   = (const float*)d_in[14];
    const float* lbhh   = (const float*)d_in[15];
    const float* oW1    = (const float*)d_in[16];
    const float* ob1    = (const float*)d_in[17];
    const float* oW2    = (const float*)d_in[18];
    const float* ob2    = (const float*)d_in[19];
    const int*   eidx   = (const int*)d_in[20];
    const int*   batch  = (const int*)d_in[21];
    float* out = (float*)d_out;

    cudaFuncSetAttribute(k_gru_mma, cudaFuncAttributeMaxDynamicSharedMemorySize,
                         GRU_SMEM);

    // order: 4th launch (ncu capture target) is k_gemmA
    k_packW2<<<(64 * 1024 + 255) / 256, 256>>>(e_W2);
    k_encode<<<(N_NODES + 255) / 256, 256>>>(nf, enc_W, enc_b);
    k_edgehid<<<(N_EDGES + 255) / 256, 256>>>(ef, e_W1, e_b1);
    k_gemmA<<<dim3(8, (N_EDGES + 127) / 128), 256>>>(e_b2);
    k_packGW<<<(192 * 64 + 255) / 256, 256>>>(gWih, gWhh);

    for (int r = 0; r < 3; r++) {
        k_message<<<(N_EDGES * 32) / 256, 256>>>(eidx);
        k_gru_mma<<<(N_NODES + 63) / 64, 256, GRU_SMEM>>>(gbih, gbhh);
    }

    k_offs<<<(N_NODES + 255) / 256, 256>>>(batch);
    k_s2s<<<(NG + 7) / 8, 256>>>(lWih, lWhh, lbih, lbhh, oW1, ob1, oW2, ob2, out);
}

// round 15
// speedup vs baseline: 1.1730x; 1.1730x over previous
#include <cuda_runtime.h>
#include <cuda_fp16.h>
#include <math_constants.h>

#define N_NODES 100000
#define N_EDGES 200000
#define NG      2000
#define H       32

typedef unsigned long long ull;

// ---------------- device scratch (alloc-free) ----------------
__device__ float  g_h[N_NODES * H];                 // node hidden fp32  12.8 MB
__device__ __half g_hh[N_NODES * H];                // node hidden fp16   6.4 MB
__device__ float  g_m[N_NODES * H];                 // aggregated msgs   12.8 MB
__device__ __half g_rh[(size_t)N_EDGES * 64];       // edge hidden fp16  25.6 MB
__device__ __half g_W2h[1024 * 64];                 // W2 fp16 transposed [n][k], 128 KB
__device__ __half g_GWh[192 * 64];                  // GRU weights fp16 block-diag
__device__ uint4  g_A4[(size_t)N_EDGES * 128];      // edge matrices fp16, 409.6 MB
__device__ int    g_offs[NG + 1];                   // graph segment offsets

// ---------------- helpers ----------------
__device__ __forceinline__ float warpMax(float v) {
    #pragma unroll
    for (int o = 16; o > 0; o >>= 1) v = fmaxf(v, __shfl_xor_sync(0xffffffffu, v, o));
    return v;
}
__device__ __forceinline__ float warpSum(float v) {
    #pragma unroll
    for (int o = 16; o > 0; o >>= 1) v += __shfl_xor_sync(0xffffffffu, v, o);
    return v;
}
__device__ __forceinline__ float sigm(float x) { return 1.0f / (1.0f + expf(-x)); }

// ---------------- W2 pack: g_W2h[n][k] = fp16(W2[k][n]) ----------------
__global__ void k_packW2(const float* __restrict__ W2) {
    int i = blockIdx.x * blockDim.x + threadIdx.x;
    if (i >= 64 * 1024) return;
    int k = i >> 10, n = i & 1023;
    g_W2h[n * 64 + k] = __float2half_rn(W2[i]);
}

// ---------------- GRU weight pack: block-diagonal [192][64] fp16 --------------
__global__ void k_packGW(const float* __restrict__ Wih, const float* __restrict__ Whh) {
    int i = blockIdx.x * blockDim.x + threadIdx.x;
    if (i >= 192 * 64) return;
    int n = i >> 6, k = i & 63;
    float v = 0.0f;
    if (n < 96 && k < 32) v = Wih[n * 32 + k];
    else if (n >= 96 && k >= 32) v = Whh[(n - 96) * 32 + (k - 32)];
    g_GWh[n * 64 + k] = __float2half_rn(v);
}

// ---------------- encoder: h = nf @ enc_W + enc_b; writes fp16 mirror; zeros m
__global__ void k_encode(const float* __restrict__ nf, const float* __restrict__ W,
                         const float* __restrict__ b) {
    __shared__ float sW[16 * 32];
    __shared__ float sb[32];
    int t = threadIdx.x;
    for (int i = t; i < 512; i += 256) sW[i] = W[i];
    if (t < 32) sb[t] = b[t];
    __syncthreads();
    int n = blockIdx.x * blockDim.x + t;
    if (n >= N_NODES) return;
    float x[16];
    const float4* p = (const float4*)(nf + (long long)n * 16);
    #pragma unroll
    for (int q = 0; q < 4; q++) {
        float4 v = p[q];
        x[q*4+0] = v.x; x[q*4+1] = v.y; x[q*4+2] = v.z; x[q*4+3] = v.w;
    }
    float hv[32];
    #pragma unroll
    for (int c = 0; c < 32; c++) {
        float acc = sb[c];
        #pragma unroll
        for (int d = 0; d < 16; d++) acc += x[d] * sW[d * 32 + c];
        hv[c] = acc;
    }
    float4* hp = (float4*)&g_h[n * 32];
    float4* mz = (float4*)&g_m[n * 32];
    __half2* hh = (__half2*)&g_hh[n * 32];
    #pragma unroll
    for (int q = 0; q < 8; q++) {
        hp[q] = make_float4(hv[q*4], hv[q*4+1], hv[q*4+2], hv[q*4+3]);
        mz[q] = make_float4(0.f, 0.f, 0.f, 0.f);
    }
    #pragma unroll
    for (int c2 = 0; c2 < 16; c2++)
        hh[c2] = __floats2half2_rn(hv[2*c2], hv[2*c2+1]);
}

// ---------------- edge hidden: rh = fp16(relu(ef @ e_W1 + e_b1)) ----------------
__global__ void k_edgehid(const float* __restrict__ ef, const float* __restrict__ W,
                          const float* __restrict__ b) {
    __shared__ float sW[8 * 64];
    __shared__ float sb[64];
    int t = threadIdx.x;
    for (int i = t; i < 512; i += 256) sW[i] = W[i];
    if (t < 64) sb[t] = b[t];
    __syncthreads();
    int e = blockIdx.x * blockDim.x + t;
    if (e >= N_EDGES) return;
    float x[8];
    const float4* p = (const float4*)(ef + (long long)e * 8);
    float4 v0 = p[0], v1 = p[1];
    x[0]=v0.x; x[1]=v0.y; x[2]=v0.z; x[3]=v0.w;
    x[4]=v1.x; x[5]=v1.y; x[6]=v1.z; x[7]=v1.w;
    float o[64];
    #pragma unroll
    for (int c = 0; c < 64; c++) {
        float acc = sb[c];
        #pragma unroll
        for (int d = 0; d < 8; d++) acc += x[d] * sW[d * 64 + c];
        o[c] = fmaxf(acc, 0.0f);
    }
    __half2* dst = (__half2*)&g_rh[(size_t)e * 64];
    #pragma unroll
    for (int c2 = 0; c2 < 32; c2++)
        dst[c2] = __floats2half2_rn(o[2 * c2], o[2 * c2 + 1]);
}

// ---------------- A GEMM (once): A[E,1024] = rh[E,64] @ W2 + b2, fp16 out ------
// BM=128, BN=128, K=64 one-shot. 8 warps (2Mx4N), warp tile 64x32.
// Epilogue FIX (R15): stage C+bias in smem (stride 136 halves, conflict-free
// STS: word idx = 4a+b mod 32 distinct), then drain with coalesced 16B
// streaming stores (256B contiguous per half-warp). sC aliases Rs/Wt.
#define ROWP 72
__global__ void __launch_bounds__(256) k_gemmA(const float* __restrict__ b2) {
    __shared__ __align__(16) unsigned char smbuf[36864];   // Rs+Wt, reused as sC
    __half* Rs = (__half*)smbuf;                 // [128][ROWP] 18432 B
    __half* Wt = (__half*)(smbuf + 18432);       // [128][ROWP] 18432 B
    __half* sC = (__half*)smbuf;                 // [128][136]  34816 B (aliased)
    int t    = threadIdx.x;
    int lane = t & 31;
    int wid  = t >> 5;
    int e0   = blockIdx.y * 128;
    int n0   = blockIdx.x * 128;
    int warpM = (wid & 1) * 64;
    int warpN = (wid >> 1) * 32;

    // load rh tile [128 x 64] fp16
    #pragma unroll
    for (int i = 0; i < 4; i++) {
        int g   = t + 256 * i;
        int row = g >> 3;
        int kg  = g & 7;
        uint4 v = make_uint4(0u, 0u, 0u, 0u);
        int e = e0 + row;
        if (e < N_EDGES) v = *(const uint4*)&g_rh[(size_t)e * 64 + kg * 8];
        *(uint4*)&Rs[row * ROWP + kg * 8] = v;
    }
    // load W2 tile [128 n x 64 k] fp16 (prepacked transposed)
    #pragma unroll
    for (int i = 0; i < 4; i++) {
        int g   = t + 256 * i;
        int row = g >> 3;
        int kg  = g & 7;
        *(uint4*)&Wt[row * ROWP + kg * 8] =
            *(const uint4*)&g_W2h[(size_t)(n0 + row) * 64 + kg * 8];
    }
    __syncthreads();

    int aRow  = warpM + (lane & 15);
    int aColB = (lane >> 4) << 3;
    int bRow  = warpN + (lane & 7) + ((lane >> 4) << 3);
    int bColB = ((lane >> 3) & 1) << 3;

    float acc[4][4][4];
    #pragma unroll
    for (int mt = 0; mt < 4; mt++)
        #pragma unroll
        for (int nt = 0; nt < 4; nt++)
            #pragma unroll
            for (int q = 0; q < 4; q++) acc[mt][nt][q] = 0.0f;

    #pragma unroll
    for (int ks = 0; ks < 4; ks++) {
        int k0 = ks * 16;
        unsigned a[4][4];
        #pragma unroll
        for (int mt = 0; mt < 4; mt++) {
            unsigned addr = (unsigned)__cvta_generic_to_shared(
                &Rs[(aRow + mt * 16) * ROWP + k0 + aColB]);
            asm volatile("ldmatrix.sync.aligned.m8n8.x4.shared.b16 {%0,%1,%2,%3}, [%4];"
                         : "=r"(a[mt][0]), "=r"(a[mt][1]), "=r"(a[mt][2]), "=r"(a[mt][3])
                         : "r"(addr));
        }
        unsigned bf[4][2];
        #pragma unroll
        for (int p = 0; p < 2; p++) {
            unsigned addr = (unsigned)__cvta_generic_to_shared(
                &Wt[(bRow + p * 16) * ROWP + k0 + bColB]);
            asm volatile("ldmatrix.sync.aligned.m8n8.x4.shared.b16 {%0,%1,%2,%3}, [%4];"
                         : "=r"(bf[2*p][0]), "=r"(bf[2*p][1]),
                           "=r"(bf[2*p+1][0]), "=r"(bf[2*p+1][1])
                         : "r"(addr));
        }
        #pragma unroll
        for (int mt = 0; mt < 4; mt++)
            #pragma unroll
            for (int nt = 0; nt < 4; nt++) {
                asm volatile(
                    "mma.sync.aligned.m16n8k16.row.col.f32.f16.f16.f32 "
                    "{%0,%1,%2,%3}, {%4,%5,%6,%7}, {%8,%9}, {%0,%1,%2,%3};"
                    : "+f"(acc[mt][nt][0]), "+f"(acc[mt][nt][1]),
                      "+f"(acc[mt][nt][2]), "+f"(acc[mt][nt][3])
                    : "r"(a[mt][0]), "r"(a[mt][1]), "r"(a[mt][2]), "r"(a[mt][3]),
                      "r"(bf[nt][0]), "r"(bf[nt][1]));
            }
    }

    // ---- epilogue: stage C (+bias) into smem, conflict-free ----
    __syncthreads();   // all warps done reading Rs/Wt
    #pragma unroll
    for (int nt = 0; nt < 4; nt++) {
        int colL = warpN + nt * 8 + (lane & 3) * 2;
        float2 bb = *(const float2*)&b2[n0 + colL];
        #pragma unroll
        for (int mt = 0; mt < 4; mt++) {
            int r0 = warpM + mt * 16 + (lane >> 2);
            *(__half2*)&sC[r0 * 136 + colL] =
                __floats2half2_rn(acc[mt][nt][0] + bb.x, acc[mt][nt][1] + bb.y);
            *(__half2*)&sC[(r0 + 8) * 136 + colL] =
                __floats2half2_rn(acc[mt][nt][2] + bb.x, acc[mt][nt][3] + bb.y);
        }
    }
    __syncthreads();

    // ---- drain: coalesced 16B streaming stores ----
    __half* gA = (__half*)g_A4;
    #pragma unroll
    for (int i = 0; i < 8; i++) {
        int idx = t + 256 * i;
        int row = idx >> 4, q = idx & 15;
        int e = e0 + row;
        if (e < N_EDGES) {
            uint4 v = *(uint4*)&sC[row * 136 + q * 8];
            __stcs((uint4*)&gA[(size_t)e * 1024 + n0 + q * 8], v);
        }
    }
}

// ---------------- message pass: m[tgt] += A[e] @ h[src] (fp16 A, streamed) -----
// one warp per edge; lane i computes msg[i] = sum_j A[e, i*32+j] * h[src, j].
// A read via __ldcs (streaming: A >> L2, keep hh + atomic lines resident).
__global__ void __launch_bounds__(256) k_message(const int* __restrict__ ei) {
    int lane = threadIdx.x & 31;
    int e = (blockIdx.x * blockDim.x + threadIdx.x) >> 5;
    if (e >= N_EDGES) return;
    int src = ei[e];
    int tgt = ei[N_EDGES + e];
    float hv = __half2float(g_hh[src * 32 + lane]);
    const uint4* Ar = g_A4 + (size_t)e * 128 + lane * 4;
    float acc = 0.0f;
    #pragma unroll
    for (int u = 0; u < 4; u++) {
        uint4 a = __ldcs(&Ar[u]);
        float2 f0 = __half22float2(*(__half2*)&a.x);
        float2 f1 = __half22float2(*(__half2*)&a.y);
        float2 f2 = __half22float2(*(__half2*)&a.z);
        float2 f3 = __half22float2(*(__half2*)&a.w);
        acc += f0.x * __shfl_sync(0xffffffffu, hv, 8*u+0);
        acc += f0.y * __shfl_sync(0xffffffffu, hv, 8*u+1);
        acc += f1.x * __shfl_sync(0xffffffffu, hv, 8*u+2);
        acc += f1.y * __shfl_sync(0xffffffffu, hv, 8*u+3);
        acc += f2.x * __shfl_sync(0xffffffffu, hv, 8*u+4);
        acc += f2.y * __shfl_sync(0xffffffffu, hv, 8*u+5);
        acc += f3.x * __shfl_sync(0xffffffffu, hv, 8*u+6);
        acc += f3.y * __shfl_sync(0xffffffffu, hv, 8*u+7);
    }
    atomicAdd(&g_m[tgt * 32 + lane], acc);
}

// ---------------- GRU via tensor cores (validated R13) ----------------
#define GRU_SMEM 87808
__global__ void __launch_bounds__(256, 2) k_gru_mma(const float* __restrict__ bih,
                                                    const float* __restrict__ bhh) {
    extern __shared__ unsigned char dsm[];
    __half* Xs    = (__half*)dsm;                      // [64][72]
    __half* Ws    = (__half*)(dsm + 9216);             // [192][72]
    float*  sGate = (float*)(dsm + 36864);             // [64][196]
    float*  sbi   = (float*)(dsm + 87040);             // [96]
    float*  sbh   = (float*)(dsm + 87424);             // [96]

    int t = threadIdx.x, lane = t & 31, wid = t >> 5;
    int n0 = blockIdx.x * 64;

    {
        int row = t >> 2, quad = t & 3;
        int node = n0 + row;
        bool ok = node < N_NODES;
        if (quad < 2) {
            const float4* mp = (const float4*)&g_m[node * 32 + quad * 16];
            #pragma unroll
            for (int q = 0; q < 2; q++) {
                float4 v0 = ok ? mp[2*q]   : make_float4(0.f,0.f,0.f,0.f);
                float4 v1 = ok ? mp[2*q+1] : make_float4(0.f,0.f,0.f,0.f);
                uint4 u;
                __half2 h0 = __floats2half2_rn(v0.x, v0.y); u.x = *(unsigned*)&h0;
                __half2 h1 = __floats2half2_rn(v0.z, v0.w); u.y = *(unsigned*)&h1;
                __half2 h2 = __floats2half2_rn(v1.x, v1.y); u.z = *(unsigned*)&h2;
                __half2 h3 = __floats2half2_rn(v1.z, v1.w); u.w = *(unsigned*)&h3;
                *(uint4*)&Xs[row * 72 + quad * 16 + q * 8] = u;
            }
        } else {
            const uint4* hp = (const uint4*)&g_hh[node * 32 + (quad - 2) * 16];
            #pragma unroll
            for (int q = 0; q < 2; q++) {
                uint4 v = ok ? hp[q] : make_uint4(0u,0u,0u,0u);
                *(uint4*)&Xs[row * 72 + 32 + (quad - 2) * 16 + q * 8] = v;
            }
        }
    }
    #pragma unroll
    for (int j = 0; j < 6; j++) {
        int i = t + 256 * j;
        int rowW = i >> 3, kg = i & 7;
        *(uint4*)&Ws[rowW * 72 + kg * 8] = *(const uint4*)&g_GWh[rowW * 64 + kg * 8];
    }
    if (t < 96) sbi[t] = bih[t];
    else if (t < 192) sbh[t - 96] = bhh[t - 96];
    __syncthreads();

    int warpM = (wid & 1) * 32;
    int warpN = (wid >> 1) * 48;
    int aRow  = warpM + (lane & 15);
    int aColB = (lane >> 4) << 3;
    int bRow  = warpN + (lane & 7) + ((lane >> 4) << 3);
    int bColB = ((lane >> 3) & 1) << 3;

    float acc[2][6][4];
    #pragma unroll
    for (int mt = 0; mt < 2; mt++)
        #pragma unroll
        for (int nt = 0; nt < 6; nt++)
            #pragma unroll
            for (int q = 0; q < 4; q++) acc[mt][nt][q] = 0.0f;

    #pragma unroll
    for (int ks = 0; ks < 4; ks++) {
        int k0 = ks * 16;
        unsigned a[2][4];
        #pragma unroll
        for (int mt = 0; mt < 2; mt++) {
            unsigned addr = (unsigned)__cvta_generic_to_shared(
                &Xs[(aRow + mt * 16) * 72 + k0 + aColB]);
            asm volatile("ldmatrix.sync.aligned.m8n8.x4.shared.b16 {%0,%1,%2,%3}, [%4];"
                         : "=r"(a[mt][0]), "=r"(a[mt][1]), "=r"(a[mt][2]), "=r"(a[mt][3])
                         : "r"(addr));
        }
        unsigned bf[6][2];
        #pragma unroll
        for (int p = 0; p < 3; p++) {
            unsigned addr = (unsigned)__cvta_generic_to_shared(
                &Ws[(bRow + p * 16) * 72 + k0 + bColB]);
            asm volatile("ldmatrix.sync.aligned.m8n8.x4.shared.b16 {%0,%1,%2,%3}, [%4];"
                         : "=r"(bf[2*p][0]), "=r"(bf[2*p][1]),
                           "=r"(bf[2*p+1][0]), "=r"(bf[2*p+1][1])
                         : "r"(addr));
        }
        #pragma unroll
        for (int mt = 0; mt < 2; mt++)
            #pragma unroll
            for (int nt = 0; nt < 6; nt++) {
                asm volatile(
                    "mma.sync.aligned.m16n8k16.row.col.f32.f16.f16.f32 "
                    "{%0,%1,%2,%3}, {%4,%5,%6,%7}, {%8,%9}, {%0,%1,%2,%3};"
                    : "+f"(acc[mt][nt][0]), "+f"(acc[mt][nt][1]),
                      "+f"(acc[mt][nt][2]), "+f"(acc[mt][nt][3])
                    : "r"(a[mt][0]), "r"(a[mt][1]), "r"(a[mt][2]), "r"(a[mt][3]),
                      "r"(bf[nt][0]), "r"(bf[nt][1]));
            }
    }

    int r0base = warpM + (lane >> 2);
    #pragma unroll
    for (int nt = 0; nt < 6; nt++) {
        int col = warpN + nt * 8 + (lane & 3) * 2;
        #pragma unroll
        for (int mt = 0; mt < 2; mt++) {
            int r0 = r0base + mt * 16;
            *(float2*)&sGate[r0 * 196 + col] = make_float2(acc[mt][nt][0], acc[mt][nt][1]);
            *(float2*)&sGate[(r0 + 8) * 196 + col] = make_float2(acc[mt][nt][2], acc[mt][nt][3]);
        }
    }
    __syncthreads();

    #pragma unroll 1
    for (int idx = t; idx < 64 * 32; idx += 256) {
        int nd = idx >> 5, k = idx & 31;
        int node = n0 + nd;
        if (node >= N_NODES) continue;
        const float* gr = &sGate[nd * 196];
        float gir = gr[k]        + sbi[k];
        float giz = gr[32 + k]   + sbi[32 + k];
        float gin = gr[64 + k]   + sbi[64 + k];
        float ghr = gr[96 + k]   + sbh[k];
        float ghz = gr[128 + k]  + sbh[32 + k];
        float ghn = gr[160 + k]  + sbh[64 + k];
        float r = sigm(gir + ghr);
        float z = sigm(giz + ghz);
        float nn = tanhf(gin + r * ghn);
        float hold = g_h[node * 32 + k];
        float hnew = (1.0f - z) * nn + z * hold;
        g_h[node * 32 + k]  = hnew;
        g_hh[node * 32 + k] = __float2half_rn(hnew);
        g_m[node * 32 + k]  = 0.0f;
    }
}

// ---------------- graph segment offsets (batch_indices sorted) ----------------
__global__ void k_offs(const int* __restrict__ batch) {
    int n = blockIdx.x * blockDim.x + threadIdx.x;
    if (n >= N_NODES) return;
    int b = batch[n];
    int prev = (n == 0) ? -1 : batch[n - 1];
    for (int g = prev + 1; g <= b; g++) g_offs[g] = n;
    if (n == N_NODES - 1)
        for (int g = b + 1; g <= NG; g++) g_offs[g] = N_NODES;
}

// ---------------- FUSED Set2Set: 4x(attend+LSTM) + output head, 1 warp/graph --
__global__ void __launch_bounds__(256) k_s2s(const float* __restrict__ lWih,
                                             const float* __restrict__ lWhh,
                                             const float* __restrict__ lbih,
                                             const float* __restrict__ lbhh,
                                             const float* __restrict__ oW1,
                                             const float* __restrict__ ob1,
                                             const float* __restrict__ oW2,
                                             const float* __restrict__ ob2,
                                             float* __restrict__ out) {
    __shared__ float sWa[128 * 33];
    __shared__ float sWb[128 * 33];
    __shared__ float sbias[128];
    __shared__ float sW1[64 * 32];
    __shared__ float sW2[96];
    __shared__ float sb1o[32];
    __shared__ float sb2o[3];
    int t = threadIdx.x, lane = t & 31, wid = t >> 5;

    for (int i = t; i < 128 * 32; i += 256) {
        int k = i >> 5, c = i & 31;
        sWa[k * 33 + c] = lWih[k * 64 + c] + lWhh[k * 32 + c];
        sWb[k * 33 + c] = lWih[k * 64 + 32 + c];
    }
    if (t < 128) sbias[t] = lbih[t] + lbhh[t];
    for (int i = t; i < 2048; i += 256) sW1[i] = oW1[i];
    if (t < 96) sW2[t] = oW2[t];
    if (t < 32) sb1o[t] = ob1[t];
    if (t < 3)  sb2o[t] = ob2[t];
    __syncthreads();

    int g = blockIdx.x * 8 + wid;
    if (g >= NG) return;
    int s = g_offs[g], tEnd = g_offs[g + 1];

    float sh = 0.0f, cst = 0.0f, rr = 0.0f;

    #pragma unroll 1
    for (int step = 0; step < 4; step++) {
        float q = sh;
        float maxv = -CUDART_INF_F, denom = 0.0f, racc = 0.0f;
        for (int base = s; base < tEnd; base += 32) {
            int n = base + lane;
            bool act = n < tEnd;
            int nn = act ? n : s;
            float rv[32];
            const float4* hp4 = (const float4*)&g_h[nn * 32];
            #pragma unroll
            for (int q4 = 0; q4 < 8; q4++) {
                float4 v = hp4[q4];
                rv[q4*4] = v.x; rv[q4*4+1] = v.y; rv[q4*4+2] = v.z; rv[q4*4+3] = v.w;
            }
            float ev = 0.0f;
            #pragma unroll
            for (int j = 0; j < 32; j++)
                ev += rv[j] * __shfl_sync(0xffffffffu, q, j);
            float e_n = act ? ev : -CUDART_INF_F;
            float cm = warpMax(e_n);
            float nm = fmaxf(maxv, cm);
            float scale = (maxv == -CUDART_INF_F) ? 0.0f : expf(maxv - nm);
            float p = act ? expf(e_n - nm) : 0.0f;
            float ps = warpSum(p);
            denom = denom * scale + ps;
            racc *= scale;
            maxv = nm;
            int cnt = min(32, tEnd - base);
            for (int n2 = 0; n2 < cnt; n2++) {
                float pn = __shfl_sync(0xffffffffu, p, n2);
                racc += pn * g_h[(base + n2) * 32 + lane];
            }
        }
        rr = (denom > 0.0f) ? (racc / denom) : 0.0f;

        float ai = sbias[lane];
        float af = sbias[32 + lane];
        float ag = sbias[64 + lane];
        float ao = sbias[96 + lane];
        #pragma unroll 1
        for (int c = 0; c < 32; c++) {
            float shv = __shfl_sync(0xffffffffu, sh, c);
            float rvv = __shfl_sync(0xffffffffu, rr, c);
            ai += shv * sWa[lane * 33 + c]        + rvv * sWb[lane * 33 + c];
            af += shv * sWa[(32 + lane) * 33 + c] + rvv * sWb[(32 + lane) * 33 + c];
            ag += shv * sWa[(64 + lane) * 33 + c] + rvv * sWb[(64 + lane) * 33 + c];
            ao += shv * sWa[(96 + lane) * 33 + c] + rvv * sWb[(96 + lane) * 33 + c];
        }
        float i_ = sigm(ai), f_ = sigm(af), gv = tanhf(ag), o_ = sigm(ao);
        cst = f_ * cst + i_ * gv;
        sh = o_ * tanhf(cst);
    }

    float hid = sb1o[lane];
    #pragma unroll 1
    for (int d = 0; d < 32; d++) {
        float shv = __shfl_sync(0xffffffffu, sh, d);
        float rvv = __shfl_sync(0xffffffffu, rr, d);
        hid += shv * sW1[d * 32 + lane] + rvv * sW1[(32 + d) * 32 + lane];
    }
    hid = fmaxf(hid, 0.0f);
    float o0 = hid * sW2[lane * 3 + 0];
    float o1 = hid * sW2[lane * 3 + 1];
    float o2 = hid * sW2[lane * 3 + 2];
    o0 = warpSum(o0); o1 = warpSum(o1); o2 = warpSum(o2);
    if (lane == 0) {
        out[g * 3 + 0] = o0 + sb2o[0];
        out[g * 3 + 1] = o1 + sb2o[1];
        out[g * 3 + 2] = o2 + sb2o[2];
    }
}

// ---------------- launch ----------------
extern "C" void kernel_launch(void* const* d_in, const int* in_sizes, int n_in,
                              void* d_out, int out_size) {
    const float* nf     = (const float*)d_in[0];
    const float* ef     = (const float*)d_in[1];
    const float* enc_W  = (const float*)d_in[2];
    const float* enc_b  = (const float*)d_in[3];
    const float* e_W1   = (const float*)d_in[4];
    const float* e_b1   = (const float*)d_in[5];
    const float* e_W2   = (const float*)d_in[6];
    const float* e_b2   = (const float*)d_in[7];
    const float* gWih   = (const float*)d_in[8];
    const float* gWhh   = (const float*)d_in[9];
    const float* gbih   = (const float*)d_in[10];
    const float* gbhh   = (const float*)d_in[11];
    const float* lWih   = (const float*)d_in[12];
    const float* lWhh   = (const float*)d_in[13];
    const float* lbih   = (const float*)d_in[14];
    const float* lbhh   = (const float*)d_in[15];
    const float* oW1    = (const float*)d_in[16];
    const float* ob1    = (const float*)d_in[17];
    const float* oW2    = (const float*)d_in[18];
    const float* ob2    = (const float*)d_in[19];
    const int*   eidx   = (const int*)d_in[20];
    const int*   batch  = (const int*)d_in[21];
    float* out = (float*)d_out;

    cudaFuncSetAttribute(k_gru_mma, cudaFuncAttributeMaxDynamicSharedMemorySize,
                         GRU_SMEM);

    // order: 4th launch (ncu capture target) is k_gemmA
    k_packW2<<<(64 * 1024 + 255) / 256, 256>>>(e_W2);
    k_encode<<<(N_NODES + 255) / 256, 256>>>(nf, enc_W, enc_b);
    k_edgehid<<<(N_EDGES + 255) / 256, 256>>>(ef, e_W1, e_b1);
    k_gemmA<<<dim3(8, (N_EDGES + 127) / 128), 256>>>(e_b2);
    k_packGW<<<(192 * 64 + 255) / 256, 256>>>(gWih, gWhh);

    for (int r = 0; r < 3; r++) {
        k_message<<<(N_EDGES * 32) / 256, 256>>>(eidx);
        k_gru_mma<<<(N_NODES + 63) / 64, 256, GRU_SMEM>>>(gbih, gbhh);
    }

    k_offs<<<(N_NODES + 255) / 256, 256>>>(batch);
    k_s2s<<<(NG + 7) / 8, 256>>>(lWih, lWhh, lbih, lbhh, oW1, ob1, oW2, ob2, out);
}